// round 3
// baseline (speedup 1.0000x reference)
#include <cuda_runtime.h>
#include <cuda_bf16.h>
#include <math.h>

// Problem constants (from reference): B=16, L=2048, D=4096, TOTAL=B*L
#define D_DIM     4096
#define D4        (D_DIM / 4)          // 1024 float4 per row
#define NSPLIT    16                   // splits along sequence dim
#define BLK       256                  // threads per block
#define NCHUNK    (D4 / BLK)           // 4 column chunks
#define B_MAX     64

// Partial sums scratch: [B][NSPLIT][D] floats. Fully overwritten every call.
__device__ float g_partial[B_MAX * NSPLIT * D_DIM];

// ---------------------------------------------------------------------------
// Kernel 1: per-(segment, split, column-chunk) masked partial sums.
// grid = (NCHUNK, NSPLIT, B), block = BLK threads.
// Each thread owns one float4 column and streams its row range.
// ---------------------------------------------------------------------------
__global__ __launch_bounds__(BLK)
void pool_partial(const float* __restrict__ hs,
                  const int* __restrict__ plens,
                  const int* __restrict__ ilens)
{
    const int chunk = blockIdx.x;   // column chunk
    const int split = blockIdx.y;   // sequence split
    const int b     = blockIdx.z;   // segment id
    const int t     = threadIdx.x;

    // segment start = exclusive cumsum of prompt_lens (B tiny; L2-resident)
    int start = 0;
    #pragma unroll 1
    for (int i = 0; i < b; ++i) start += plens[i];
    const int plen = plens[b];
    const int il   = ilens[b];

    // row range for this split, clipped below by instruction_len
    const int rps = (plen + NSPLIT - 1) / NSPLIT;
    int r0 = split * rps;
    int r1 = r0 + rps; if (r1 > plen) r1 = plen;
    if (r0 < il) r0 = il;

    const int col = chunk * BLK + t;             // float4 column index
    const float4* __restrict__ hs4 = (const float4*)hs;

    float4 acc = make_float4(0.f, 0.f, 0.f, 0.f);

    int r = r0;
    // unrolled by 4 for memory-level parallelism
    for (; r + 4 <= r1; r += 4) {
        size_t base = (size_t)(start + r) * D4 + col;
        float4 v0 = hs4[base];
        float4 v1 = hs4[base + D4];
        float4 v2 = hs4[base + 2 * (size_t)D4];
        float4 v3 = hs4[base + 3 * (size_t)D4];
        acc.x += v0.x + v1.x + v2.x + v3.x;
        acc.y += v0.y + v1.y + v2.y + v3.y;
        acc.z += v0.z + v1.z + v2.z + v3.z;
        acc.w += v0.w + v1.w + v2.w + v3.w;
    }
    for (; r < r1; ++r) {
        float4 v = hs4[(size_t)(start + r) * D4 + col];
        acc.x += v.x; acc.y += v.y; acc.z += v.z; acc.w += v.w;
    }

    float4* __restrict__ part = (float4*)g_partial;
    part[((size_t)b * NSPLIT + split) * D4 + col] = acc;
}

// ---------------------------------------------------------------------------
// Kernel 2: reduce NSPLIT partials -> mean, L2-normalize, write output.
// grid = B, block = BLK. Each thread owns NCHUNK float4 columns.
// ---------------------------------------------------------------------------
__global__ __launch_bounds__(BLK)
void pool_finalize(const int* __restrict__ plens,
                   const int* __restrict__ ilens,
                   float* __restrict__ out)
{
    const int b = blockIdx.x;
    const int t = threadIdx.x;

    const float cnt = (float)(plens[b] - ilens[b]);
    const float inv = 1.0f / cnt;

    const float4* __restrict__ part = (const float4*)g_partial;

    float4 mean[NCHUNK];
    float sq = 0.f;

    #pragma unroll
    for (int c = 0; c < NCHUNK; ++c) {
        const int col = c * BLK + t;
        float4 s = make_float4(0.f, 0.f, 0.f, 0.f);
        #pragma unroll
        for (int sp = 0; sp < NSPLIT; ++sp) {
            float4 v = part[((size_t)b * NSPLIT + sp) * D4 + col];
            s.x += v.x; s.y += v.y; s.z += v.z; s.w += v.w;
        }
        s.x *= inv; s.y *= inv; s.z *= inv; s.w *= inv;
        mean[c] = s;
        sq += s.x * s.x + s.y * s.y + s.z * s.z + s.w * s.w;
    }

    // block reduce sum of squares
    __shared__ float red[BLK];
    red[t] = sq;
    __syncthreads();
    #pragma unroll
    for (int off = BLK / 2; off > 0; off >>= 1) {
        if (t < off) red[t] += red[t + off];
        __syncthreads();
    }
    const float norm = sqrtf(red[0]);
    const float rn = 1.0f / fmaxf(norm, 1e-12f);

    float4* __restrict__ o4 = (float4*)out;
    #pragma unroll
    for (int c = 0; c < NCHUNK; ++c) {
        const int col = c * BLK + t;
        float4 m = mean[c];
        m.x *= rn; m.y *= rn; m.z *= rn; m.w *= rn;
        o4[(size_t)b * D4 + col] = m;
    }
}

extern "C" void kernel_launch(void* const* d_in, const int* in_sizes, int n_in,
                              void* d_out, int out_size)
{
    const float* hs    = (const float*)d_in[0];
    const int*   plens = (const int*)d_in[1];
    const int*   ilens = (const int*)d_in[2];
    float*       out   = (float*)d_out;

    const int B = in_sizes[1];   // number of sequences

    dim3 grid1(NCHUNK, NSPLIT, B);
    pool_partial<<<grid1, BLK>>>(hs, plens, ilens);

    pool_finalize<<<B, BLK>>>(plens, ilens, out);
}